// round 5
// baseline (speedup 1.0000x reference)
#include <cuda_runtime.h>
#include <cstdint>

#define BATCH   32
#define NA      9
#define HW      4096
#define NPROP   (HW*NA)          // 36864
#define NVEC    (NPROP/4)        // 9216 float4 per batch
#define TOPK    300
#define OUTC    66
#define CAP     2048

// key threshold for score >= 2.0f  (~840 candidates/batch expected)
#define THR_FAST 0xC0000000u

// Anchor (w,h) table; centers are always (8+16*gx, 8+16*gy)
__constant__ float c_aw[9] = {92.f,184.f,368.f,64.f,128.f,256.f,44.f,88.f,176.f};
__constant__ float c_ah[9] = {48.f,96.f,192.f,64.f,128.f,256.f,88.f,176.f,352.f};

__device__ int                g_cnt[BATCH * 32];      // stride-32 ints: 128B apart
__device__ unsigned long long g_cand[BATCH * CAP];
__device__ unsigned           g_dec[BATCH * TOPK];    // n | (rank<<16), ascending n

__device__ __forceinline__ unsigned f2key(float s) {
    unsigned u = __float_as_uint(s);
    return (u & 0x80000000u) ? ~u : (u | 0x80000000u);
}

// ---------------------------------------------------------------------------
// Stage 1: full-chip streaming compact with fixed threshold. 8 CTAs/batch.
// ---------------------------------------------------------------------------
__global__ __launch_bounds__(512)
void compact_kernel(const float* __restrict__ scores_in)
{
    const int b = blockIdx.y;
    const float4* sp = (const float4*)(scores_in + (size_t)b * 18 * HW + (size_t)NA * HW);

    for (int i = blockIdx.x * 512 + threadIdx.x; i < NVEC; i += 8 * 512) {
        float4 v = sp[i];
        float vv[4] = {v.x, v.y, v.z, v.w};
        #pragma unroll
        for (int j = 0; j < 4; j++) {
            unsigned k = f2key(vv[j]);
            if (k >= THR_FAST) {
                int idx = 4 * i + j;               // memory order: a*4096 + hw
                int a = idx >> 12, hw = idx & 4095;
                int n = hw * 9 + a;                // jax flat order
                int pos = atomicAdd(&g_cnt[b * 32], 1);
                if (pos < CAP)
                    g_cand[b * CAP + pos] =
                        ((unsigned long long)k << 32) | (unsigned)(~n);
            }
        }
    }
}

// ---------------------------------------------------------------------------
// Stage 2: exact rank-by-count (+ exact histogram fallback). 1 CTA/batch.
// ---------------------------------------------------------------------------
__global__ __launch_bounds__(1024, 1)
void rank_kernel(const float* __restrict__ scores_in, float* __restrict__ out)
{
    __shared__ unsigned long long cand[CAP];     // 16 KB
    __shared__ unsigned hist[4096];              // 16 KB (fallback only)
    __shared__ unsigned sel_n[TOPK];
    __shared__ unsigned wsum[32], wpre[32];
    __shared__ unsigned s_thr;
    __shared__ int s_cnt;

    const int b = blockIdx.x;
    const int tid = threadIdx.x;
    const unsigned lane = tid & 31u;
    const int warp = tid >> 5;

    int C = g_cnt[b * 32];
    const float4* sp = (const float4*)(scores_in + (size_t)b * 18 * HW + (size_t)NA * HW);

    if (C >= TOPK && C <= CAP) {
        for (int i = tid; i < C; i += 1024)
            cand[i] = g_cand[b * CAP + i];
        __syncthreads();
    } else {
        // ---- exact fallback: histogram select over the scores ----
        #pragma unroll
        for (int i = tid; i < 4096; i += 1024) hist[i] = 0;
        if (tid == 0) s_cnt = 0;
        __syncthreads();
        #pragma unroll 3
        for (int i = tid; i < NVEC; i += 1024) {
            float4 v = sp[i];
            atomicAdd(&hist[f2key(v.x) >> 20], 1u);
            atomicAdd(&hist[f2key(v.y) >> 20], 1u);
            atomicAdd(&hist[f2key(v.z) >> 20], 1u);
            atomicAdd(&hist[f2key(v.w) >> 20], 1u);
        }
        __syncthreads();
        const int bhi = 4095 - 4 * tid;
        unsigned h0 = hist[bhi],     h1 = hist[bhi - 1];
        unsigned h2 = hist[bhi - 2], h3 = hist[bhi - 3];
        unsigned s = h0 + h1 + h2 + h3;
        unsigned incl = s;
        #pragma unroll
        for (int o = 1; o < 32; o <<= 1) {
            unsigned v = __shfl_up_sync(0xFFFFFFFFu, incl, o);
            if (lane >= o) incl += v;
        }
        if (lane == 31) wsum[warp] = incl;
        __syncthreads();
        if (warp == 0) {
            unsigned w = wsum[lane];
            unsigned wi = w;
            #pragma unroll
            for (int o = 1; o < 32; o <<= 1) {
                unsigned v = __shfl_up_sync(0xFFFFFFFFu, wi, o);
                if (lane >= o) wi += v;
            }
            wpre[lane] = wi - w;
        }
        __syncthreads();
        {
            unsigned c = wpre[warp] + (incl - s);
            unsigned hh[4] = {h0, h1, h2, h3};
            #pragma unroll
            for (int j = 0; j < 4; j++) {
                if (c < TOPK && c + hh[j] >= TOPK)
                    s_thr = ((unsigned)(bhi - j)) << 20;
                c += hh[j];
            }
        }
        __syncthreads();
        const unsigned thr = s_thr;
        #pragma unroll 3
        for (int i = tid; i < NVEC; i += 1024) {
            float4 v = sp[i];
            float vv[4] = {v.x, v.y, v.z, v.w};
            #pragma unroll
            for (int j = 0; j < 4; j++) {
                unsigned k = f2key(vv[j]);
                if (k >= thr) {
                    int idx = 4 * i + j;
                    int a = idx >> 12, hw = idx & 4095;
                    int n = hw * 9 + a;
                    int pos = atomicAdd(&s_cnt, 1);
                    if (pos < CAP)
                        cand[pos] = ((unsigned long long)k << 32) | (unsigned)(~n);
                }
            }
        }
        __syncthreads();
        C = min(s_cnt, CAP);
    }

    // ---- exact rank by counting (keys unique -> jax tie-break preserved) ----
    for (int i = tid; i < C; i += 1024) {
        const unsigned long long me = cand[i];
        int r = 0;
        for (int j = 0; j < C; j++) r += (cand[j] > me);   // smem broadcast
        if (r < TOPK) {
            unsigned n = (unsigned)(~(unsigned)me) & 0xFFFFu;
            sel_n[r] = n;
            unsigned k32 = (unsigned)(me >> 32);
            unsigned u = (k32 & 0x80000000u) ? (k32 & 0x7FFFFFFFu) : ~k32;
            size_t row = ((size_t)b * TOPK + r) * OUTC;
            out[row + 0] = (float)b;
            out[row + OUTC - 1] = __uint_as_float(u);
        }
    }
    __syncthreads();

    // decode feed in ascending flat-index order (gather locality)
    if (tid < TOPK) {
        unsigned n = sel_n[tid];
        int o = 0;
        for (int j = 0; j < TOPK; j++) o += (sel_n[j] < n);
        g_dec[b * TOPK + o] = n | ((unsigned)tid << 16);
    }
}

// ---------------------------------------------------------------------------
// Decode (R2-proven shape): 8 proposals per 512-thread block.
// ---------------------------------------------------------------------------
__global__ __launch_bounds__(512)
void decode_kernel(const float* __restrict__ bbox,
                   const float* __restrict__ im_info,
                   float* __restrict__ out)
{
    const int tid = threadIdx.x;
    const int j = blockIdx.x * 8 + (tid >> 6);
    const int b = blockIdx.y;
    const int k = tid & 63;
    if (j >= TOPK) return;                     // 64-thread groups: warp-uniform

    const unsigned packed = g_dec[b * TOPK + j];
    const int n    = packed & 0xFFFFu;
    const int rank = packed >> 16;

    const int a  = n % 9;
    const int hw = n / 9;
    const float w  = c_aw[a];
    const float h  = c_ah[a];
    const float cx = 8.0f + 16.0f * (float)(hw & 63);
    const float cy = 8.0f + 16.0f * (float)(hw >> 6);

    const float d = __ldcs(&bbox[((size_t)b * 576 + (size_t)a * 64 + k) * HW + hw]);

    const unsigned base = (tid & 31u) & ~3u;
    const float d0 = __shfl_sync(0xFFFFFFFFu, d, base + 0);
    const float d1 = __shfl_sync(0xFFFFFFFFu, d, base + 1);
    const float d2 = __shfl_sync(0xFFFFFFFFu, d, base + 2);
    const float d3 = __shfl_sync(0xFFFFFFFFu, d, base + 3);

    const float xmax = im_info[b * 3 + 1] - 1.0f;
    const float ymax = im_info[b * 3 + 0] - 1.0f;

    const float pcx = d0 * w + cx;
    const float pcy = d1 * h + cy;
    const float pw  = expf(d2) * w;
    const float ph  = expf(d3) * h;

    float v;
    switch (k & 3) {
        case 0: v = fminf(fmaxf(pcx - 0.5f * pw, 0.0f), xmax); break;
        case 1: v = fminf(fmaxf(pcy - 0.5f * ph, 0.0f), ymax); break;
        case 2: v = fminf(fmaxf(pcx + 0.5f * pw, 0.0f), xmax); break;
        default: v = fminf(fmaxf(pcy + 0.5f * ph, 0.0f), ymax); break;
    }

    out[((size_t)b * TOPK + rank) * OUTC + 1 + k] = v;
}

extern "C" void kernel_launch(void* const* d_in, const int* in_sizes, int n_in,
                              void* d_out, int out_size)
{
    const float* scores  = (const float*)d_in[0];  // (32,18,64,64)
    const float* bbox    = (const float*)d_in[1];  // (32,576,64,64)
    const float* im_info = (const float*)d_in[2];  // (32,3)
    float* out = (float*)d_out;                    // (32,300,66)

    void* cnt_ptr = nullptr;
    cudaGetSymbolAddress(&cnt_ptr, g_cnt);
    cudaMemsetAsync(cnt_ptr, 0, sizeof(int) * BATCH * 32, 0);

    compact_kernel<<<dim3(8, BATCH), 512>>>(scores);
    rank_kernel<<<BATCH, 1024>>>(scores, out);
    decode_kernel<<<dim3((TOPK + 7) / 8, BATCH), 512>>>(bbox, im_info, out);
}

// round 7
// speedup vs baseline: 1.1328x; 1.1328x over previous
#include <cuda_runtime.h>
#include <cstdint>

#define BATCH   32
#define NA      9
#define HW      4096
#define NPROP   (HW*NA)          // 36864
#define NVEC    (NPROP/4)        // 9216 float4 per batch
#define TOPK    300
#define OUTC    66
#define CAP     2048
#define NCTA    16               // compact CTAs per batch
#define LCAP    1024             // per-CTA staging capacity

// key threshold for score >= 2.0f  (~840 candidates/batch expected)
#define THR_FAST 0xC0000000u

// Anchor (w,h) table; centers are always (8+16*gx, 8+16*gy)
__constant__ float c_aw[9] = {92.f,184.f,368.f,64.f,128.f,256.f,44.f,88.f,176.f};
__constant__ float c_ah[9] = {48.f,96.f,192.f,64.f,128.f,256.f,88.f,176.f,352.f};

__device__ int                g_cnt[BATCH * 32];      // stride-32: 128B apart
__device__ unsigned long long g_cand[BATCH * CAP];
__device__ unsigned           g_dec[BATCH * TOPK];    // n | (rank<<16), asc n

__device__ __forceinline__ unsigned f2key(float s) {
    unsigned u = __float_as_uint(s);
    return (u & 0x80000000u) ? ~u : (u | 0x80000000u);
}

// ---------------------------------------------------------------------------
// Stage 1: full-chip streaming compact, two-phase (smem staging -> one
// global atomic per CTA -> coalesced chunk copy). 16 CTAs/batch.
// ---------------------------------------------------------------------------
__global__ __launch_bounds__(512)
void compact_kernel(const float* __restrict__ scores_in)
{
    __shared__ unsigned long long buf[LCAP];
    __shared__ int s_cnt;
    __shared__ int s_base;

    const int b = blockIdx.y;
    const int tid = threadIdx.x;
    if (tid == 0) s_cnt = 0;
    __syncthreads();

    const float4* sp = (const float4*)(scores_in + (size_t)b * 18 * HW + (size_t)NA * HW);

    for (int i = blockIdx.x * 512 + tid; i < NVEC; i += NCTA * 512) {
        float4 v = sp[i];
        float vv[4] = {v.x, v.y, v.z, v.w};
        #pragma unroll
        for (int j = 0; j < 4; j++) {
            unsigned k = f2key(vv[j]);
            if (k >= THR_FAST) {
                int idx = 4 * i + j;               // memory order: a*4096 + hw
                int a = idx >> 12, hw = idx & 4095;
                int n = hw * 9 + a;                // jax flat order
                int pos = atomicAdd(&s_cnt, 1);    // smem atomic: cheap
                if (pos < LCAP)
                    buf[pos] = ((unsigned long long)k << 32) | (unsigned)(~n);
            }
        }
    }
    __syncthreads();

    const int cnt = s_cnt;                          // block-uniform after sync
    if (cnt > LCAP) {
        // staging overflow (impossible for benign inputs): force exact fallback
        if (tid == 0) atomicAdd(&g_cnt[b * 32], CAP + 1);
        return;
    }
    if (tid == 0) s_base = atomicAdd(&g_cnt[b * 32], cnt);  // ONE global RMW
    __syncthreads();
    const int base = s_base;

    for (int i = tid; i < cnt; i += 512) {
        int pos = base + i;
        if (pos < CAP) g_cand[b * CAP + pos] = buf[i];
    }
}

// ---------------------------------------------------------------------------
// Stage 2: exact rank-by-count (+ exact histogram fallback). 1 CTA/batch.
// Resets the batch counter for the next graph replay.
// ---------------------------------------------------------------------------
__global__ __launch_bounds__(1024, 1)
void rank_kernel(const float* __restrict__ scores_in, float* __restrict__ out)
{
    __shared__ unsigned long long cand[CAP];     // 16 KB
    __shared__ unsigned hist[4096];              // 16 KB (fallback only)
    __shared__ unsigned sel_n[TOPK];
    __shared__ unsigned wsum[32], wpre[32];
    __shared__ unsigned s_thr;
    __shared__ int s_cnt;
    __shared__ int s_C;

    const int b = blockIdx.x;
    const int tid = threadIdx.x;
    const unsigned lane = tid & 31u;
    const int warp = tid >> 5;

    // Broadcast the candidate count BEFORE resetting it (block-uniform branch).
    if (tid == 0) s_C = g_cnt[b * 32];
    __syncthreads();
    int C = s_C;
    if (tid == 0) g_cnt[b * 32] = 0;             // reset for next replay

    const float4* sp = (const float4*)(scores_in + (size_t)b * 18 * HW + (size_t)NA * HW);

    if (C >= TOPK && C <= CAP) {
        for (int i = tid; i < C; i += 1024)
            cand[i] = g_cand[b * CAP + i];
        __syncthreads();
    } else {
        // ---- exact fallback: histogram select over the scores ----
        #pragma unroll
        for (int i = tid; i < 4096; i += 1024) hist[i] = 0;
        if (tid == 0) s_cnt = 0;
        __syncthreads();
        #pragma unroll 3
        for (int i = tid; i < NVEC; i += 1024) {
            float4 v = sp[i];
            atomicAdd(&hist[f2key(v.x) >> 20], 1u);
            atomicAdd(&hist[f2key(v.y) >> 20], 1u);
            atomicAdd(&hist[f2key(v.z) >> 20], 1u);
            atomicAdd(&hist[f2key(v.w) >> 20], 1u);
        }
        __syncthreads();
        const int bhi = 4095 - 4 * tid;
        unsigned h0 = hist[bhi],     h1 = hist[bhi - 1];
        unsigned h2 = hist[bhi - 2], h3 = hist[bhi - 3];
        unsigned s = h0 + h1 + h2 + h3;
        unsigned incl = s;
        #pragma unroll
        for (int o = 1; o < 32; o <<= 1) {
            unsigned v = __shfl_up_sync(0xFFFFFFFFu, incl, o);
            if (lane >= o) incl += v;
        }
        if (lane == 31) wsum[warp] = incl;
        __syncthreads();
        if (warp == 0) {
            unsigned w = wsum[lane];
            unsigned wi = w;
            #pragma unroll
            for (int o = 1; o < 32; o <<= 1) {
                unsigned v = __shfl_up_sync(0xFFFFFFFFu, wi, o);
                if (lane >= o) wi += v;
            }
            wpre[lane] = wi - w;
        }
        __syncthreads();
        {
            unsigned c = wpre[warp] + (incl - s);
            unsigned hh[4] = {h0, h1, h2, h3};
            #pragma unroll
            for (int j = 0; j < 4; j++) {
                if (c < TOPK && c + hh[j] >= TOPK)
                    s_thr = ((unsigned)(bhi - j)) << 20;
                c += hh[j];
            }
        }
        __syncthreads();
        const unsigned thr = s_thr;
        #pragma unroll 3
        for (int i = tid; i < NVEC; i += 1024) {
            float4 v = sp[i];
            float vv[4] = {v.x, v.y, v.z, v.w};
            #pragma unroll
            for (int j = 0; j < 4; j++) {
                unsigned k = f2key(vv[j]);
                if (k >= thr) {
                    int idx = 4 * i + j;
                    int a = idx >> 12, hw = idx & 4095;
                    int n = hw * 9 + a;
                    int pos = atomicAdd(&s_cnt, 1);
                    if (pos < CAP)
                        cand[pos] = ((unsigned long long)k << 32) | (unsigned)(~n);
                }
            }
        }
        __syncthreads();
        C = min(s_cnt, CAP);
    }

    // ---- exact rank by counting (unique keys -> jax tie-break preserved) ----
    for (int i = tid; i < C; i += 1024) {
        const unsigned long long me = cand[i];
        int r = 0;
        for (int j = 0; j < C; j++) r += (cand[j] > me);   // smem broadcast
        if (r < TOPK) {
            unsigned n = (unsigned)(~(unsigned)me) & 0xFFFFu;
            sel_n[r] = n;
            unsigned k32 = (unsigned)(me >> 32);
            unsigned u = (k32 & 0x80000000u) ? (k32 & 0x7FFFFFFFu) : ~k32;
            size_t row = ((size_t)b * TOPK + r) * OUTC;
            out[row + 0] = (float)b;
            out[row + OUTC - 1] = __uint_as_float(u);
        }
    }
    __syncthreads();

    // decode feed in ascending flat-index order (gather locality)
    if (tid < TOPK) {
        unsigned n = sel_n[tid];
        int o = 0;
        for (int j = 0; j < TOPK; j++) o += (sel_n[j] < n);
        g_dec[b * TOPK + o] = n | ((unsigned)tid << 16);
    }
}

// ---------------------------------------------------------------------------
// Decode (R2-proven shape): 8 proposals per 512-thread block.
// ---------------------------------------------------------------------------
__global__ __launch_bounds__(512)
void decode_kernel(const float* __restrict__ bbox,
                   const float* __restrict__ im_info,
                   float* __restrict__ out)
{
    const int tid = threadIdx.x;
    const int j = blockIdx.x * 8 + (tid >> 6);
    const int b = blockIdx.y;
    const int k = tid & 63;
    if (j >= TOPK) return;                     // 64-thread groups: warp-uniform

    const unsigned packed = g_dec[b * TOPK + j];
    const int n    = packed & 0xFFFFu;
    const int rank = packed >> 16;

    const int a  = n % 9;
    const int hw = n / 9;
    const float w  = c_aw[a];
    const float h  = c_ah[a];
    const float cx = 8.0f + 16.0f * (float)(hw & 63);
    const float cy = 8.0f + 16.0f * (float)(hw >> 6);

    const float d = __ldcs(&bbox[((size_t)b * 576 + (size_t)a * 64 + k) * HW + hw]);

    const unsigned base = (tid & 31u) & ~3u;
    const float d0 = __shfl_sync(0xFFFFFFFFu, d, base + 0);
    const float d1 = __shfl_sync(0xFFFFFFFFu, d, base + 1);
    const float d2 = __shfl_sync(0xFFFFFFFFu, d, base + 2);
    const float d3 = __shfl_sync(0xFFFFFFFFu, d, base + 3);

    const float xmax = im_info[b * 3 + 1] - 1.0f;
    const float ymax = im_info[b * 3 + 0] - 1.0f;

    const float pcx = d0 * w + cx;
    const float pcy = d1 * h + cy;
    const float pw  = expf(d2) * w;
    const float ph  = expf(d3) * h;

    float v;
    switch (k & 3) {
        case 0: v = fminf(fmaxf(pcx - 0.5f * pw, 0.0f), xmax); break;
        case 1: v = fminf(fmaxf(pcy - 0.5f * ph, 0.0f), ymax); break;
        case 2: v = fminf(fmaxf(pcx + 0.5f * pw, 0.0f), xmax); break;
        default: v = fminf(fmaxf(pcy + 0.5f * ph, 0.0f), ymax); break;
    }

    out[((size_t)b * TOPK + rank) * OUTC + 1 + k] = v;
}

extern "C" void kernel_launch(void* const* d_in, const int* in_sizes, int n_in,
                              void* d_out, int out_size)
{
    const float* scores  = (const float*)d_in[0];  // (32,18,64,64)
    const float* bbox    = (const float*)d_in[1];  // (32,576,64,64)
    const float* im_info = (const float*)d_in[2];  // (32,3)
    float* out = (float*)d_out;                    // (32,300,66)

    compact_kernel<<<dim3(NCTA, BATCH), 512>>>(scores);
    rank_kernel<<<BATCH, 1024>>>(scores, out);
    decode_kernel<<<dim3((TOPK + 7) / 8, BATCH), 512>>>(bbox, im_info, out);
}